// round 2
// baseline (speedup 1.0000x reference)
#include <cuda_runtime.h>
#include <cstdint>
#include <cstddef>

// ---------------- scratch (static device arrays: allowed) ----------------
__device__ float g_Q[4096u * 4096u];   // projected Q  [tok][32*128]
__device__ float g_K[4096u * 1024u];   // projected K  [tok][8*128]
__device__ float g_V[4096u * 1024u];   // projected V  [tok][8*128]
__device__ float g_ctx[4096u * 4096u]; // attention out [tok][32*128]

// ---------------- helpers ----------------
__device__ __forceinline__ uint32_t f2tf(float x) {
    uint32_t u;
    asm("cvt.rna.tf32.f32 %0, %1;" : "=r"(u) : "f"(x));
    return u;
}

// =========================================================================
// TF32 GEMM:  C[M,N] = A[M,K] @ B[N,K]^T   (A row-major, B = weights [N][K])
// Block tile 128x64, K-tile 32, 256 threads (8 warps: 4 in M, 2 in N),
// warp tile 32x32 = 2x4 mma(m16n8k8) tiles. Double-buffered smem.
// All dims divisible: M%128==0, N%64==0, K%32==0.
// =========================================================================
#define GA_STR 36  // 32 + 4 pad (floats)

__global__ void __launch_bounds__(256)
gemm_tf32(float* __restrict__ C, const float* __restrict__ A,
          const float* __restrict__ B, int M, int N, int K)
{
    extern __shared__ float sm[];
    float* As = sm;                  // 2 * 128*36
    float* Bs = sm + 2 * 128 * GA_STR; // 2 * 64*36

    const int tid  = threadIdx.x;
    const int warp = tid >> 5, lane = tid & 31;
    const int wm = warp & 3, wn = warp >> 2;
    const int bm = blockIdx.y * 128, bn = blockIdx.x * 64;

    float acc[2][4][4];
#pragma unroll
    for (int i = 0; i < 2; i++)
#pragma unroll
        for (int j = 0; j < 4; j++)
#pragma unroll
            for (int t = 0; t < 4; t++) acc[i][j][t] = 0.f;

    const int kTiles = K >> 5;

    float4 ra[4], rb[2];

    auto loadA = [&](int kt) {
        const float* Ag = A + (size_t)bm * K + kt * 32;
#pragma unroll
        for (int i = 0; i < 4; i++) {
            int f = tid + i * 256;
            int r = f >> 3, c4 = (f & 7) << 2;
            ra[i] = *(const float4*)(Ag + (size_t)r * K + c4);
        }
    };
    auto loadB = [&](int kt) {
        const float* Bg = B + (size_t)bn * K + kt * 32;
#pragma unroll
        for (int i = 0; i < 2; i++) {
            int f = tid + i * 256;
            int r = f >> 3, c4 = (f & 7) << 2;
            rb[i] = *(const float4*)(Bg + (size_t)r * K + c4);
        }
    };
    auto storeA = [&](float* dst) {
#pragma unroll
        for (int i = 0; i < 4; i++) {
            int f = tid + i * 256;
            int r = f >> 3, c4 = (f & 7) << 2;
            float4 t;
            t.x = __uint_as_float(f2tf(ra[i].x));
            t.y = __uint_as_float(f2tf(ra[i].y));
            t.z = __uint_as_float(f2tf(ra[i].z));
            t.w = __uint_as_float(f2tf(ra[i].w));
            *(float4*)(dst + r * GA_STR + c4) = t;
        }
    };
    auto storeB = [&](float* dst) {
#pragma unroll
        for (int i = 0; i < 2; i++) {
            int f = tid + i * 256;
            int r = f >> 3, c4 = (f & 7) << 2;
            float4 t;
            t.x = __uint_as_float(f2tf(rb[i].x));
            t.y = __uint_as_float(f2tf(rb[i].y));
            t.z = __uint_as_float(f2tf(rb[i].z));
            t.w = __uint_as_float(f2tf(rb[i].w));
            *(float4*)(dst + r * GA_STR + c4) = t;
        }
    };
    auto compute = [&](const float* As_, const float* Bs_) {
#pragma unroll
        for (int ks = 0; ks < 32; ks += 8) {
            uint32_t a[2][4], b[4][2];
#pragma unroll
            for (int mt = 0; mt < 2; mt++) {
                int r0 = wm * 32 + mt * 16 + (lane >> 2);
                int c0 = ks + (lane & 3);
                a[mt][0] = __float_as_uint(As_[r0 * GA_STR + c0]);
                a[mt][1] = __float_as_uint(As_[(r0 + 8) * GA_STR + c0]);
                a[mt][2] = __float_as_uint(As_[r0 * GA_STR + c0 + 4]);
                a[mt][3] = __float_as_uint(As_[(r0 + 8) * GA_STR + c0 + 4]);
            }
#pragma unroll
            for (int nt = 0; nt < 4; nt++) {
                int n0 = wn * 32 + nt * 8 + (lane >> 2);
                int k0 = ks + (lane & 3);
                b[nt][0] = __float_as_uint(Bs_[n0 * GA_STR + k0]);
                b[nt][1] = __float_as_uint(Bs_[n0 * GA_STR + k0 + 4]);
            }
#pragma unroll
            for (int mt = 0; mt < 2; mt++)
#pragma unroll
                for (int nt = 0; nt < 4; nt++) {
                    float* c = acc[mt][nt];
                    asm volatile(
                        "mma.sync.aligned.m16n8k8.row.col.f32.tf32.tf32.f32 "
                        "{%0,%1,%2,%3}, {%4,%5,%6,%7}, {%8,%9}, {%0,%1,%2,%3};\n"
                        : "+f"(c[0]), "+f"(c[1]), "+f"(c[2]), "+f"(c[3])
                        : "r"(a[mt][0]), "r"(a[mt][1]), "r"(a[mt][2]), "r"(a[mt][3]),
                          "r"(b[nt][0]), "r"(b[nt][1]));
                }
        }
    };

    loadA(0); loadB(0);
    storeA(As); storeB(Bs);
    __syncthreads();

    for (int kt = 0; kt < kTiles; kt++) {
        int cur = kt & 1, nxt = cur ^ 1;
        if (kt + 1 < kTiles) { loadA(kt + 1); loadB(kt + 1); }
        compute(As + cur * 128 * GA_STR, Bs + cur * 64 * GA_STR);
        if (kt + 1 < kTiles) {
            storeA(As + nxt * 128 * GA_STR);
            storeB(Bs + nxt * 64 * GA_STR);
        }
        __syncthreads();
    }

#pragma unroll
    for (int mt = 0; mt < 2; mt++) {
        int r0 = bm + wm * 32 + mt * 16 + (lane >> 2);
#pragma unroll
        for (int nt = 0; nt < 4; nt++) {
            int c0 = bn + wn * 32 + nt * 8 + ((lane & 3) << 1);
            float* c = acc[mt][nt];
            C[(size_t)r0 * N + c0]           = c[0];
            C[(size_t)r0 * N + c0 + 1]       = c[1];
            C[(size_t)(r0 + 8) * N + c0]     = c[2];
            C[(size_t)(r0 + 8) * N + c0 + 1] = c[3];
        }
    }
}

// =========================================================================
// RoPE (in place).  X: [4096 tok][heads*128], pos = tok % 2048.
// grid (4096, heads), 64 threads = 64 rotation pairs.
// =========================================================================
__global__ void rope_kernel(float* __restrict__ X, int ld)
{
    int tok = blockIdx.x;
    int h   = blockIdx.y;
    int d   = threadIdx.x;            // 0..63
    int s   = tok & 2047;
    float inv = powf(10000.0f, -(float)d * (1.0f / 64.0f));
    float ang = (float)s * inv;
    float sn, cs;
    sincosf(ang, &sn, &cs);
    float* p = X + (size_t)tok * ld + h * 128;
    float x1 = p[d], x2 = p[d + 64];
    p[d]      = x1 * cs - x2 * sn;
    p[d + 64] = x2 * cs + x1 * sn;
}

// =========================================================================
// Causal flash attention (fp32 SIMT), GQA 32Q/8KV heads, D=128.
// Block = (qtile of 64 rows, head, batch), 256 threads (8 warps).
// Warp w owns output rows w*8..w*8+7; lane owns 4 output cols (lane*4..+3)
// for PV, and score cols {lane, lane+32} for QK.
// =========================================================================
#define QS_STR 132   // 128 + 4 pad
#define SS_STR 68    // 64 + 4 pad

__global__ void __launch_bounds__(256)
attn_kernel(float* __restrict__ ctx, const float* __restrict__ Qg,
            const float* __restrict__ Kg, const float* __restrict__ Vg)
{
    extern __shared__ float sm[];
    float* Qs   = sm;                     // 64*132
    float* Ks   = Qs + 64 * QS_STR;       // 64*132
    float* Vs   = Ks + 64 * QS_STR;       // 64*132
    float* Ss   = Vs + 64 * QS_STR;       // 64*68
    float* m_sm = Ss + 64 * SS_STR;       // 64
    float* l_sm = m_sm + 64;              // 64
    float* a_sm = l_sm + 64;              // 64

    const int tid  = threadIdx.x;
    const int warp = tid >> 5, lane = tid & 31;
    const int qt = 31 - (int)blockIdx.x;   // big tiles first (causal balance)
    const int h  = blockIdx.y;
    const int b  = blockIdx.z;
    const int hkv = h >> 2;
    const float scale = 0.08838834764831845f;  // 1/sqrt(128)

    // ---- load Q tile (scaled) ----
    const float* Qp = Qg + ((size_t)(b * 2048 + qt * 64)) * 4096 + h * 128;
#pragma unroll
    for (int i = 0; i < 8; i++) {
        int f = tid + i * 256;             // over 2048 float4
        int r = f >> 5, c4 = (f & 31) << 2;
        float4 v = *(const float4*)(Qp + (size_t)r * 4096 + c4);
        float* p = Qs + r * QS_STR + c4;
        p[0] = v.x * scale; p[1] = v.y * scale;
        p[2] = v.z * scale; p[3] = v.w * scale;
    }
    if (tid < 64) { m_sm[tid] = -3.0e38f; l_sm[tid] = 0.f; }

    float O[8][4];
#pragma unroll
    for (int i = 0; i < 8; i++)
#pragma unroll
        for (int j = 0; j < 4; j++) O[i][j] = 0.f;

    __syncthreads();

    for (int kt = 0; kt <= qt; kt++) {
        // ---- load K,V tiles ----
        const float* Kp = Kg + ((size_t)(b * 2048 + kt * 64)) * 1024 + hkv * 128;
        const float* Vp = Vg + ((size_t)(b * 2048 + kt * 64)) * 1024 + hkv * 128;
#pragma unroll
        for (int i = 0; i < 8; i++) {
            int f = tid + i * 256;
            int r = f >> 5, c4 = (f & 31) << 2;
            *(float4*)(Ks + r * QS_STR + c4) = *(const float4*)(Kp + (size_t)r * 1024 + c4);
            *(float4*)(Vs + r * QS_STR + c4) = *(const float4*)(Vp + (size_t)r * 1024 + c4);
        }
        __syncthreads();

        // ---- S = Qs @ Ks^T ----
        {
            float s0[8], s1[8];
#pragma unroll
            for (int i = 0; i < 8; i++) { s0[i] = 0.f; s1[i] = 0.f; }
            const float* qb = Qs + (warp * 8) * QS_STR;
            const float* k0 = Ks + lane * QS_STR;
            const float* k1 = Ks + (lane + 32) * QS_STR;
#pragma unroll 2
            for (int k = 0; k < 128; k += 4) {
                float4 kk0 = *(const float4*)(k0 + k);
                float4 kk1 = *(const float4*)(k1 + k);
#pragma unroll
                for (int i = 0; i < 8; i++) {
                    float4 q = *(const float4*)(qb + i * QS_STR + k);
                    s0[i] += q.x * kk0.x + q.y * kk0.y + q.z * kk0.z + q.w * kk0.w;
                    s1[i] += q.x * kk1.x + q.y * kk1.y + q.z * kk1.z + q.w * kk1.w;
                }
            }
            bool diag = (kt == qt);
#pragma unroll
            for (int i = 0; i < 8; i++) {
                int r = warp * 8 + i;
                float v0 = s0[i], v1 = s1[i];
                if (diag) {
                    if (lane > r)      v0 = -3.0e38f;
                    if (lane + 32 > r) v1 = -3.0e38f;
                }
                Ss[r * SS_STR + lane]      = v0;
                Ss[r * SS_STR + lane + 32] = v1;
            }
        }
        __syncthreads();

        // ---- online softmax: 4 lanes per row ----
        {
            int row = tid >> 2, seg = tid & 3;
            float* srow = Ss + row * SS_STR;
            float mx = -3.0e38f;
#pragma unroll
            for (int c = 0; c < 16; c++) mx = fmaxf(mx, srow[seg * 16 + c]);
            mx = fmaxf(mx, __shfl_xor_sync(0xffffffffu, mx, 1));
            mx = fmaxf(mx, __shfl_xor_sync(0xffffffffu, mx, 2));
            float m_old = m_sm[row];
            float m_new = fmaxf(m_old, mx);
            float sum = 0.f;
#pragma unroll
            for (int c = 0; c < 16; c++) {
                float p = __expf(srow[seg * 16 + c] - m_new);
                srow[seg * 16 + c] = p;
                sum += p;
            }
            sum += __shfl_xor_sync(0xffffffffu, sum, 1);
            sum += __shfl_xor_sync(0xffffffffu, sum, 2);
            if (seg == 0) {
                float alpha = __expf(m_old - m_new);
                l_sm[row] = l_sm[row] * alpha + sum;
                m_sm[row] = m_new;
                a_sm[row] = alpha;
            }
        }
        __syncthreads();

        // ---- O = O*alpha + P @ V ----
        {
            const float* prow = Ss + (warp * 8) * SS_STR;
#pragma unroll
            for (int i = 0; i < 8; i++) {
                float al = a_sm[warp * 8 + i];
#pragma unroll
                for (int j = 0; j < 4; j++) O[i][j] *= al;
            }
#pragma unroll 2
            for (int k = 0; k < 64; k += 4) {
                float4 v0 = *(const float4*)(Vs + (k + 0) * QS_STR + lane * 4);
                float4 v1 = *(const float4*)(Vs + (k + 1) * QS_STR + lane * 4);
                float4 v2 = *(const float4*)(Vs + (k + 2) * QS_STR + lane * 4);
                float4 v3 = *(const float4*)(Vs + (k + 3) * QS_STR + lane * 4);
#pragma unroll
                for (int i = 0; i < 8; i++) {
                    float4 p = *(const float4*)(prow + i * SS_STR + k);
                    O[i][0] += p.x * v0.x + p.y * v1.x + p.z * v2.x + p.w * v3.x;
                    O[i][1] += p.x * v0.y + p.y * v1.y + p.z * v2.y + p.w * v3.y;
                    O[i][2] += p.x * v0.z + p.y * v1.z + p.z * v2.z + p.w * v3.z;
                    O[i][3] += p.x * v0.w + p.y * v1.w + p.z * v2.w + p.w * v3.w;
                }
            }
        }
        __syncthreads();
    }

    // ---- normalize + write ctx ----
    float* Cp = ctx + ((size_t)(b * 2048 + qt * 64)) * 4096 + h * 128;
#pragma unroll
    for (int i = 0; i < 8; i++) {
        int r = warp * 8 + i;
        float inv_l = 1.0f / l_sm[r];
        float4 o;
        o.x = O[i][0] * inv_l; o.y = O[i][1] * inv_l;
        o.z = O[i][2] * inv_l; o.w = O[i][3] * inv_l;
        *(float4*)(Cp + (size_t)r * 4096 + lane * 4) = o;
    }
}

// =========================================================================
// launcher
// =========================================================================
extern "C" void kernel_launch(void* const* d_in, const int* in_sizes, int n_in,
                              void* d_out, int out_size)
{
    const float* q  = (const float*)d_in[0];
    const float* k  = (const float*)d_in[1];
    const float* v  = (const float*)d_in[2];
    const float* Wq = (const float*)d_in[3];
    const float* Wk = (const float*)d_in[4];
    const float* Wv = (const float*)d_in[5];
    const float* Wd = (const float*)d_in[6];
    float* out = (float*)d_out;

    float *Qp, *Kp, *Vp, *Cp;
    cudaGetSymbolAddress((void**)&Qp, g_Q);
    cudaGetSymbolAddress((void**)&Kp, g_K);
    cudaGetSymbolAddress((void**)&Vp, g_V);
    cudaGetSymbolAddress((void**)&Cp, g_ctx);

    const int GEMM_SMEM = 2 * (128 * GA_STR + 64 * GA_STR) * 4;       // 55296
    const int ATTN_SMEM = (3 * 64 * QS_STR + 64 * SS_STR + 192) * 4;  // 119552
    cudaFuncSetAttribute(gemm_tf32,  cudaFuncAttributeMaxDynamicSharedMemorySize, GEMM_SMEM);
    cudaFuncSetAttribute(attn_kernel, cudaFuncAttributeMaxDynamicSharedMemorySize, ATTN_SMEM);

    // projections (M = 4096 tokens)
    gemm_tf32<<<dim3(4096 / 64, 4096 / 128), 256, GEMM_SMEM>>>(Qp, q, Wq, 4096, 4096, 4096);
    gemm_tf32<<<dim3(1024 / 64, 4096 / 128), 256, GEMM_SMEM>>>(Kp, k, Wk, 4096, 1024, 4096);
    gemm_tf32<<<dim3(1024 / 64, 4096 / 128), 256, GEMM_SMEM>>>(Vp, v, Wv, 4096, 1024, 4096);

    // RoPE
    rope_kernel<<<dim3(4096, 32), 64>>>(Qp, 4096);
    rope_kernel<<<dim3(4096, 8),  64>>>(Kp, 1024);

    // attention
    attn_kernel<<<dim3(32, 32, 2), 256, ATTN_SMEM>>>(Cp, Qp, Kp, Vp);

    // output projection
    gemm_tf32<<<dim3(4096 / 64, 4096 / 128), 256, GEMM_SMEM>>>(out, Cp, Wd, 4096, 4096, 4096);
}

// round 5
// speedup vs baseline: 1.7487x; 1.7487x over previous
#include <cuda_runtime.h>
#include <cstdint>
#include <cstddef>

// ---------------- scratch ----------------
__device__ float g_Q[4096u * 4096u];
__device__ float g_K[4096u * 1024u];
__device__ float g_V[4096u * 1024u];
__device__ float g_ctx[4096u * 4096u];

// ---------------- helpers ----------------
__device__ __forceinline__ uint32_t f2tf(float x) {
    uint32_t u;
    asm("cvt.rna.tf32.f32 %0, %1;" : "=r"(u) : "f"(x));
    return u;
}
__device__ __forceinline__ float4 tf4(float4 v) {
    float4 t;
    t.x = __uint_as_float(f2tf(v.x)); t.y = __uint_as_float(f2tf(v.y));
    t.z = __uint_as_float(f2tf(v.z)); t.w = __uint_as_float(f2tf(v.w));
    return t;
}
__device__ __forceinline__ void mma_tf32(float* c, uint32_t a0, uint32_t a1,
                                         uint32_t a2, uint32_t a3,
                                         uint32_t b0, uint32_t b1) {
    asm volatile(
        "mma.sync.aligned.m16n8k8.row.col.f32.tf32.tf32.f32 "
        "{%0,%1,%2,%3}, {%4,%5,%6,%7}, {%8,%9}, {%0,%1,%2,%3};\n"
        : "+f"(c[0]), "+f"(c[1]), "+f"(c[2]), "+f"(c[3])
        : "r"(a0), "r"(a1), "r"(a2), "r"(a3), "r"(b0), "r"(b1));
}

// =========================================================================
// TF32 GEMM v2:  C[M,N] = A[M,K] @ B[N,K]^T
// Block 128x128, K-tile 32, 256 threads (8 warps: 2 in M x 4 in N),
// warp tile 64x32 = 4x4 mma(m16n8k8). Double-buffered smem.
// =========================================================================
#define GA_STR 36  // 32 + 4 pad

__global__ void __launch_bounds__(256)
gemm_tf32(float* __restrict__ C, const float* __restrict__ A,
          const float* __restrict__ B, int M, int N, int K)
{
    extern __shared__ float sm[];
    float* As = sm;                        // 2 * 128*36
    float* Bs = sm + 2 * 128 * GA_STR;     // 2 * 128*36

    const int tid  = threadIdx.x;
    const int warp = tid >> 5, lane = tid & 31;
    const int wm = warp & 1, wn = warp >> 1;
    const int bm = blockIdx.y * 128, bn = blockIdx.x * 128;

    float acc[4][4][4];
#pragma unroll
    for (int i = 0; i < 4; i++)
#pragma unroll
        for (int j = 0; j < 4; j++)
#pragma unroll
            for (int t = 0; t < 4; t++) acc[i][j][t] = 0.f;

    const int kTiles = K >> 5;
    float4 ra[4], rb[4];

    auto loadA = [&](int kt) {
        const float* Ag = A + (size_t)bm * K + kt * 32;
#pragma unroll
        for (int i = 0; i < 4; i++) {
            int f = tid + i * 256;
            int r = f >> 3, c4 = (f & 7) << 2;
            ra[i] = *(const float4*)(Ag + (size_t)r * K + c4);
        }
    };
    auto loadB = [&](int kt) {
        const float* Bg = B + (size_t)bn * K + kt * 32;
#pragma unroll
        for (int i = 0; i < 4; i++) {
            int f = tid + i * 256;
            int r = f >> 3, c4 = (f & 7) << 2;
            rb[i] = *(const float4*)(Bg + (size_t)r * K + c4);
        }
    };
    auto storeAB = [&](float* Ad, float* Bd) {
#pragma unroll
        for (int i = 0; i < 4; i++) {
            int f = tid + i * 256;
            int r = f >> 3, c4 = (f & 7) << 2;
            *(float4*)(Ad + r * GA_STR + c4) = tf4(ra[i]);
            *(float4*)(Bd + r * GA_STR + c4) = tf4(rb[i]);
        }
    };
    auto compute = [&](const float* As_, const float* Bs_) {
#pragma unroll
        for (int ks = 0; ks < 32; ks += 8) {
            uint32_t a[4][4], b[4][2];
#pragma unroll
            for (int mt = 0; mt < 4; mt++) {
                int r0 = wm * 64 + mt * 16 + (lane >> 2);
                int c0 = ks + (lane & 3);
                a[mt][0] = __float_as_uint(As_[r0 * GA_STR + c0]);
                a[mt][1] = __float_as_uint(As_[(r0 + 8) * GA_STR + c0]);
                a[mt][2] = __float_as_uint(As_[r0 * GA_STR + c0 + 4]);
                a[mt][3] = __float_as_uint(As_[(r0 + 8) * GA_STR + c0 + 4]);
            }
#pragma unroll
            for (int nt = 0; nt < 4; nt++) {
                int n0 = wn * 32 + nt * 8 + (lane >> 2);
                int k0 = ks + (lane & 3);
                b[nt][0] = __float_as_uint(Bs_[n0 * GA_STR + k0]);
                b[nt][1] = __float_as_uint(Bs_[n0 * GA_STR + k0 + 4]);
            }
#pragma unroll
            for (int mt = 0; mt < 4; mt++)
#pragma unroll
                for (int nt = 0; nt < 4; nt++)
                    mma_tf32(acc[mt][nt], a[mt][0], a[mt][1], a[mt][2], a[mt][3],
                             b[nt][0], b[nt][1]);
        }
    };

    loadA(0); loadB(0);
    storeAB(As, Bs);
    __syncthreads();

    for (int kt = 0; kt < kTiles; kt++) {
        int cur = kt & 1, nxt = cur ^ 1;
        if (kt + 1 < kTiles) { loadA(kt + 1); loadB(kt + 1); }
        compute(As + cur * 128 * GA_STR, Bs + cur * 128 * GA_STR);
        if (kt + 1 < kTiles)
            storeAB(As + nxt * 128 * GA_STR, Bs + nxt * 128 * GA_STR);
        __syncthreads();
    }

#pragma unroll
    for (int mt = 0; mt < 4; mt++) {
        int r0 = bm + wm * 64 + mt * 16 + (lane >> 2);
#pragma unroll
        for (int nt = 0; nt < 4; nt++) {
            int c0 = bn + wn * 32 + nt * 8 + ((lane & 3) << 1);
            float* c = acc[mt][nt];
            *(float2*)(C + (size_t)r0 * N + c0)       = make_float2(c[0], c[1]);
            *(float2*)(C + (size_t)(r0 + 8) * N + c0) = make_float2(c[2], c[3]);
        }
    }
}

// =========================================================================
// RoPE (in place)
// =========================================================================
__global__ void rope_kernel(float* __restrict__ X, int ld)
{
    int tok = blockIdx.x, h = blockIdx.y, d = threadIdx.x;
    int s = tok & 2047;
    float inv = powf(10000.0f, -(float)d * (1.0f / 64.0f));
    float ang = (float)s * inv;
    float sn, cs;
    sincosf(ang, &sn, &cs);
    float* p = X + (size_t)tok * ld + h * 128;
    float x1 = p[d], x2 = p[d + 64];
    p[d]      = x1 * cs - x2 * sn;
    p[d + 64] = x2 * cs + x1 * sn;
}

// =========================================================================
// Causal flash attention with tf32 mma for QK^T and PV.
// Block = (qtile 64 rows, head, batch), 256 threads (8 warps).
// QK: warp (mq = w&3 -> 16 rows, nh = w>>2 -> 32 cols), S via smem.
// Softmax: fp32 (R2 code). PV: warp (mq = w&3 -> 16 rows, nd = w>>2 -> 64 d).
// =========================================================================
#define QS_STR 132   // Q/K smem stride (conflict-free frag reads)
#define VS_STR 136   // V smem stride (conflict-free column reads)
#define SS_STR 68    // S/P smem stride

__global__ void __launch_bounds__(256)
attn_kernel(float* __restrict__ ctx, const float* __restrict__ Qg,
            const float* __restrict__ Kg, const float* __restrict__ Vg)
{
    extern __shared__ float sm[];
    float* Qs   = sm;                     // 64*132
    float* Ks   = Qs + 64 * QS_STR;       // 64*132
    float* Vs   = Ks + 64 * QS_STR;       // 64*136
    float* Ss   = Vs + 64 * VS_STR;       // 64*68
    float* m_sm = Ss + 64 * SS_STR;       // 64
    float* l_sm = m_sm + 64;              // 64
    float* a_sm = l_sm + 64;              // 64

    const int tid  = threadIdx.x;
    const int warp = tid >> 5, lane = tid & 31;
    const int lq = lane >> 2;             // 0..7
    const int lr = lane & 3;              // 0..3
    const int qt = 31 - (int)blockIdx.x;  // big tiles first
    const int h  = blockIdx.y;
    const int b  = blockIdx.z;
    const int hkv = h >> 2;
    const float scale = 0.08838834764831845f;

    const int mq = warp & 3;              // 16-row block
    const int wh = warp >> 2;             // 0..1

    // ---- load Q tile (scaled + tf32) ----
    const float* Qp = Qg + ((size_t)(b * 2048 + qt * 64)) * 4096 + h * 128;
#pragma unroll
    for (int i = 0; i < 8; i++) {
        int f = tid + i * 256;
        int r = f >> 5, c4 = (f & 31) << 2;
        float4 v = *(const float4*)(Qp + (size_t)r * 4096 + c4);
        v.x *= scale; v.y *= scale; v.z *= scale; v.w *= scale;
        *(float4*)(Qs + r * QS_STR + c4) = tf4(v);
    }
    if (tid < 64) { m_sm[tid] = -3.0e38f; l_sm[tid] = 0.f; }

    float O[8][4];                         // PV accum: 8 n8-tiles over 64 d-cols
#pragma unroll
    for (int i = 0; i < 8; i++)
#pragma unroll
        for (int j = 0; j < 4; j++) O[i][j] = 0.f;

    __syncthreads();

    for (int kt = 0; kt <= qt; kt++) {
        // ---- load K (tf32), V (tf32) ----
        const float* Kp = Kg + ((size_t)(b * 2048 + kt * 64)) * 1024 + hkv * 128;
        const float* Vp = Vg + ((size_t)(b * 2048 + kt * 64)) * 1024 + hkv * 128;
#pragma unroll
        for (int i = 0; i < 8; i++) {
            int f = tid + i * 256;
            int r = f >> 5, c4 = (f & 31) << 2;
            *(float4*)(Ks + r * QS_STR + c4) = tf4(*(const float4*)(Kp + (size_t)r * 1024 + c4));
            *(float4*)(Vs + r * VS_STR + c4) = tf4(*(const float4*)(Vp + (size_t)r * 1024 + c4));
        }
        __syncthreads();

        // ---- S = Q @ K^T via mma (warp: rows mq*16..+15, cols wh*32..+31) ----
        {
            float sacc[4][4];
#pragma unroll
            for (int nt = 0; nt < 4; nt++)
#pragma unroll
                for (int t = 0; t < 4; t++) sacc[nt][t] = 0.f;

            const int r0 = mq * 16 + lq;
#pragma unroll
            for (int ks = 0; ks < 128; ks += 8) {
                int c0 = ks + lr;
                uint32_t a0 = __float_as_uint(Qs[r0 * QS_STR + c0]);
                uint32_t a1 = __float_as_uint(Qs[(r0 + 8) * QS_STR + c0]);
                uint32_t a2 = __float_as_uint(Qs[r0 * QS_STR + c0 + 4]);
                uint32_t a3 = __float_as_uint(Qs[(r0 + 8) * QS_STR + c0 + 4]);
#pragma unroll
                for (int nt = 0; nt < 4; nt++) {
                    int n0 = wh * 32 + nt * 8 + lq;
                    uint32_t b0 = __float_as_uint(Ks[n0 * QS_STR + c0]);
                    uint32_t b1 = __float_as_uint(Ks[n0 * QS_STR + c0 + 4]);
                    mma_tf32(sacc[nt], a0, a1, a2, a3, b0, b1);
                }
            }
            // mask + write S to smem
            bool diag = (kt == qt);
#pragma unroll
            for (int nt = 0; nt < 4; nt++) {
                int c = wh * 32 + nt * 8 + 2 * lr;
                float v0 = sacc[nt][0], v1 = sacc[nt][1];
                float v2 = sacc[nt][2], v3 = sacc[nt][3];
                int ra = mq * 16 + lq, rb2 = ra + 8;
                if (diag) {
                    if (c > ra)     v0 = -3.0e38f;
                    if (c + 1 > ra) v1 = -3.0e38f;
                    if (c > rb2)     v2 = -3.0e38f;
                    if (c + 1 > rb2) v3 = -3.0e38f;
                }
                *(float2*)(Ss + ra * SS_STR + c)  = make_float2(v0, v1);
                *(float2*)(Ss + rb2 * SS_STR + c) = make_float2(v2, v3);
            }
        }
        __syncthreads();

        // ---- online softmax (4 lanes per row), P stored as tf32 ----
        {
            int row = tid >> 2, seg = tid & 3;
            float* srow = Ss + row * SS_STR;
            float mx = -3.0e38f;
#pragma unroll
            for (int c = 0; c < 16; c++) mx = fmaxf(mx, srow[seg * 16 + c]);
            mx = fmaxf(mx, __shfl_xor_sync(0xffffffffu, mx, 1));
            mx = fmaxf(mx, __shfl_xor_sync(0xffffffffu, mx, 2));
            float m_old = m_sm[row];
            float m_new = fmaxf(m_old, mx);
            float sum = 0.f;
#pragma unroll
            for (int c = 0; c < 16; c++) {
                float p = __expf(srow[seg * 16 + c] - m_new);
                srow[seg * 16 + c] = __uint_as_float(f2tf(p));
                sum += p;
            }
            sum += __shfl_xor_sync(0xffffffffu, sum, 1);
            sum += __shfl_xor_sync(0xffffffffu, sum, 2);
            if (seg == 0) {
                float alpha = __expf(m_old - m_new);
                l_sm[row] = l_sm[row] * alpha + sum;
                m_sm[row] = m_new;
                a_sm[row] = alpha;
            }
        }
        __syncthreads();

        // ---- O = O*alpha + P @ V via mma (warp: rows mq*16..+15, d-cols wh*64..+63)
        {
            const int ra = mq * 16 + lq;
            float al0 = a_sm[ra], al1 = a_sm[ra + 8];
#pragma unroll
            for (int nt = 0; nt < 8; nt++) {
                O[nt][0] *= al0; O[nt][1] *= al0;
                O[nt][2] *= al1; O[nt][3] *= al1;
            }
#pragma unroll
            for (int ks = 0; ks < 64; ks += 8) {
                int c0 = ks + lr;
                uint32_t a0 = __float_as_uint(Ss[ra * SS_STR + c0]);
                uint32_t a1 = __float_as_uint(Ss[(ra + 8) * SS_STR + c0]);
                uint32_t a2 = __float_as_uint(Ss[ra * SS_STR + c0 + 4]);
                uint32_t a3 = __float_as_uint(Ss[(ra + 8) * SS_STR + c0 + 4]);
#pragma unroll
                for (int nt = 0; nt < 8; nt++) {
                    int n = wh * 64 + nt * 8 + lq;          // d column
                    uint32_t b0 = __float_as_uint(Vs[c0 * VS_STR + n]);
                    uint32_t b1 = __float_as_uint(Vs[(c0 + 4) * VS_STR + n]);
                    mma_tf32(O[nt], a0, a1, a2, a3, b0, b1);
                }
            }
        }
        __syncthreads();
    }

    // ---- normalize + write ctx ----
    {
        const int ra = mq * 16 + lq;
        float inv0 = 1.0f / l_sm[ra];
        float inv1 = 1.0f / l_sm[ra + 8];
        float* Cp = ctx + ((size_t)(b * 2048 + qt * 64)) * 4096 + h * 128;
#pragma unroll
        for (int nt = 0; nt < 8; nt++) {
            int c = wh * 64 + nt * 8 + 2 * lr;
            *(float2*)(Cp + (size_t)ra * 4096 + c)       = make_float2(O[nt][0] * inv0, O[nt][1] * inv0);
            *(float2*)(Cp + (size_t)(ra + 8) * 4096 + c) = make_float2(O[nt][2] * inv1, O[nt][3] * inv1);
        }
    }
}

// =========================================================================
// launcher
// =========================================================================
extern "C" void kernel_launch(void* const* d_in, const int* in_sizes, int n_in,
                              void* d_out, int out_size)
{
    const float* q  = (const float*)d_in[0];
    const float* k  = (const float*)d_in[1];
    const float* v  = (const float*)d_in[2];
    const float* Wq = (const float*)d_in[3];
    const float* Wk = (const float*)d_in[4];
    const float* Wv = (const float*)d_in[5];
    const float* Wd = (const float*)d_in[6];
    float* out = (float*)d_out;

    float *Qp, *Kp, *Vp, *Cp;
    cudaGetSymbolAddress((void**)&Qp, g_Q);
    cudaGetSymbolAddress((void**)&Kp, g_K);
    cudaGetSymbolAddress((void**)&Vp, g_V);
    cudaGetSymbolAddress((void**)&Cp, g_ctx);

    const int GEMM_SMEM = 2 * 2 * 128 * GA_STR * 4;                       // 73728
    const int ATTN_SMEM = (2 * 64 * QS_STR + 64 * VS_STR + 64 * SS_STR + 192) * 4;
    cudaFuncSetAttribute(gemm_tf32,   cudaFuncAttributeMaxDynamicSharedMemorySize, GEMM_SMEM);
    cudaFuncSetAttribute(attn_kernel, cudaFuncAttributeMaxDynamicSharedMemorySize, ATTN_SMEM);

    // projections
    gemm_tf32<<<dim3(4096 / 128, 32), 256, GEMM_SMEM>>>(Qp, q, Wq, 4096, 4096, 4096);
    gemm_tf32<<<dim3(1024 / 128, 32), 256, GEMM_SMEM>>>(Kp, k, Wk, 4096, 1024, 4096);
    gemm_tf32<<<dim3(1024 / 128, 32), 256, GEMM_SMEM>>>(Vp, v, Wv, 4096, 1024, 4096);

    // RoPE
    rope_kernel<<<dim3(4096, 32), 64>>>(Qp, 4096);
    rope_kernel<<<dim3(4096, 8),  64>>>(Kp, 1024);

    // attention
    attn_kernel<<<dim3(32, 32, 2), 256, ATTN_SMEM>>>(Cp, Qp, Kp, Vp);

    // output projection
    gemm_tf32<<<dim3(4096 / 128, 32), 256, GEMM_SMEM>>>(out, Cp, Wd, 4096, 4096, 4096);
}